// round 15
// baseline (speedup 1.0000x reference)
#include <cuda_runtime.h>
#include <cuda_fp16.h>
#include <cstdint>

// SoftAddressSpace: out[M,V] = softmax(selector[M,D] @ AS[N,D]^T) @ PB[N,V]
// M=16384, D=128, N=4096, V=512, fp32 in/out.
// R14: single-term fp16 pass1 (filter grade) + exact rescore in pass2.
//   Count model (validated R10-R13): survivors(theta) ~ e^{Delta/2.8}.
//   theta=5e-6 -> ~77 survivors << LCAP 272 (the R10/R11 overflow bug is
//   structurally avoided).
//   pass1: 1-term fp16 HMMA + online softmax -> approx p fp16, R, SINV.
//   pass2: suffix-scan R -> scale; compact cols w_approx > 5e-6; EXACT fp32
//          rescore (selector . AS); exact softmax; fp16 PB gather.

#define M_TOT  16384
#define N_ADDR 4096
#define D_DIM  128
#define V_DIM  512
#define NTILES (N_ADDR / 128)   // 32
#define LCAP   272              // per-row survivor capacity
#define FTHR   5e-6f            // filter threshold on approx weight

static __device__ __half g_p   [(size_t)M_TOT * N_ADDR];   // fp16 approx p (128 MiB)
static __device__ __half g_ash [(size_t)N_ADDR * D_DIM];   // AS fp16 (1 MiB)
static __device__ __half g_pbh [(size_t)N_ADDR * V_DIM];   // PB fp16 (4 MiB)
static __device__ float  g_r   [(size_t)NTILES * M_TOT];   // rescale, [t][row]
static __device__ float  g_sinv[(size_t)M_TOT];            // 1/sum per row

__device__ __forceinline__ uint32_t smem_u32(const void* p) {
    uint32_t a;
    asm("{ .reg .u64 t; cvta.to.shared.u64 t, %1; cvt.u32.u64 %0, t; }" : "=r"(a) : "l"(p));
    return a;
}

#define LDSM_X4(r0, r1, r2, r3, addr) \
    asm volatile("ldmatrix.sync.aligned.m8n8.x4.shared.b16 {%0,%1,%2,%3}, [%4];" \
                 : "=r"(r0), "=r"(r1), "=r"(r2), "=r"(r3) : "r"(addr))

__device__ __forceinline__ void mma16816(float* d, const uint32_t* a, const uint32_t* b) {
    asm volatile(
        "mma.sync.aligned.m16n8k16.row.col.f32.f16.f16.f32 "
        "{%0,%1,%2,%3}, {%4,%5,%6,%7}, {%8,%9}, {%0,%1,%2,%3};"
        : "+f"(d[0]), "+f"(d[1]), "+f"(d[2]), "+f"(d[3])
        : "r"(a[0]), "r"(a[1]), "r"(a[2]), "r"(a[3]), "r"(b[0]), "r"(b[1]));
}

__device__ __forceinline__ void cp16(uint32_t dst, const void* src) {
    asm volatile("cp.async.cg.shared.global [%0], [%1], 16;" :: "r"(dst), "l"(src));
}
#define CP_COMMIT() asm volatile("cp.async.commit_group;" ::: "memory")
#define CP_WAIT0()  asm volatile("cp.async.wait_group 0;" ::: "memory")

// ---------------------------------------------------------------------------
// Pass 1: grid = 128 CTAs, warp w owns rows [w*16, w*16+16).
// Smem: Sh @0 (32K), B stages @32K (2 x 32K) = 96K -> 2 CTAs/SM.
// 256B rows; swizzle off ^ (((off>>8)&7)<<4). Single-term fp16 MMA;
// R9's proven online-softmax epilogue (branch-free).
// ---------------------------------------------------------------------------
__global__ __launch_bounds__(256, 2) void score_pass(
    const float* __restrict__ S, const __half* __restrict__ ASh,
    __half* __restrict__ P, float* __restrict__ R, float* __restrict__ SINV)
{
    extern __shared__ char sm[];
    const uint32_t sb = smem_u32(sm);
    const int tid = threadIdx.x, lane = tid & 31, wid = tid >> 5;
    const int m0 = blockIdx.x * 128;
    const int sub = lane >> 3, rr = lane & 7;
    const int lg = lane >> 2, lt = lane & 3;
    const int wrow = wid * 16;

    // --- load + convert selector strip (fp16, resident) ---
#pragma unroll
    for (int s = 0; s < 8; s++) {
        int idx = tid + s * 256;
        int r = idx >> 4, b = idx & 15;
        uint32_t off = (uint32_t)(r * 256 + b * 16);
        uint32_t sw = off ^ (((off >> 8) & 7) << 4);
        const float* src = S + (size_t)(m0 + r) * D_DIM + b * 8;
        float4 v0 = *(const float4*)src, v1 = *(const float4*)(src + 4);
        __half2 h0 = __floats2half2_rn(v0.x, v0.y);
        __half2 h1 = __floats2half2_rn(v0.z, v0.w);
        __half2 h2 = __floats2half2_rn(v1.x, v1.y);
        __half2 h3 = __floats2half2_rn(v1.z, v1.w);
        *(uint4*)(sm + sw) = make_uint4(*(uint32_t*)&h0, *(uint32_t*)&h1,
                                        *(uint32_t*)&h2, *(uint32_t*)&h3);
    }

    auto issueB = [&](int st, int t) {
        const uint32_t base = 32768u + (uint32_t)st * 32768u;
#pragma unroll
        for (int s = 0; s < 8; s++) {
            int idx = tid + s * 256;
            int r = idx >> 4, b = idx & 15;
            uint32_t off = (uint32_t)(r * 256 + b * 16);
            uint32_t sw = off ^ (((off >> 8) & 7) << 4);
            cp16(sb + base + sw, ASh + (size_t)(t * 128 + r) * D_DIM + b * 8);
        }
        CP_COMMIT();
    };

    issueB(0, 0);

    float m_run[2] = {-1e30f, -1e30f}, s_run[2] = {0.0f, 0.0f};

    for (int t = 0; t < NTILES; t++) {
        CP_WAIT0();
        __syncthreads();
        if (t + 1 < NTILES) issueB((t + 1) & 1, t + 1);

        const uint32_t bbase = sb + 32768u + (uint32_t)(t & 1) * 32768u;

        float acc[16][4];
#pragma unroll
        for (int i = 0; i < 16; i++)
#pragma unroll
            for (int k = 0; k < 4; k++) acc[i][k] = 0.0f;

#pragma unroll
        for (int ks = 0; ks < 8; ks++) {
            uint32_t ah[4], bh[32];
            {
                int row = wrow + ((sub & 1) << 3) + rr;
                uint32_t off = (uint32_t)(row * 256 + ks * 32 + ((sub >> 1) << 4));
                uint32_t sw = off ^ (((off >> 8) & 7) << 4);
                LDSM_X4(ah[0], ah[1], ah[2], ah[3], sb + sw);
            }
#pragma unroll
            for (int p2 = 0; p2 < 8; p2++) {
                int nrow = p2 * 16 + ((sub >> 1) << 3) + rr;
                uint32_t off = (uint32_t)(nrow * 256 + ks * 32 + ((sub & 1) << 4));
                uint32_t sw = off ^ (((off >> 8) & 7) << 4);
                LDSM_X4(bh[p2 * 4], bh[p2 * 4 + 1], bh[p2 * 4 + 2], bh[p2 * 4 + 3], bbase + sw);
            }
#pragma unroll
            for (int nf = 0; nf < 16; nf++)
                mma16816(acc[nf], ah, &bh[nf * 2]);
        }

        // --- warp-local online softmax (rows: wrow+lg, wrow+lg+8) ---
        float mnew[2], rfac[2], tsum[2];
#pragma unroll
        for (int h = 0; h < 2; h++) {
            float v = -1e30f;
#pragma unroll
            for (int nf = 0; nf < 16; nf++)
                v = fmaxf(v, fmaxf(acc[nf][2 * h], acc[nf][2 * h + 1]));
            v = fmaxf(v, __shfl_xor_sync(0xffffffffu, v, 1));
            v = fmaxf(v, __shfl_xor_sync(0xffffffffu, v, 2));
            float mn = fmaxf(m_run[h], v);
            mnew[h] = mn;
            rfac[h] = __expf(m_run[h] - mn);
            s_run[h] *= rfac[h];
            tsum[h] = 0.0f;
        }
#pragma unroll
        for (int nf = 0; nf < 16; nf++) {
            acc[nf][0] = __expf(acc[nf][0] - mnew[0]);
            acc[nf][1] = __expf(acc[nf][1] - mnew[0]);
            acc[nf][2] = __expf(acc[nf][2] - mnew[1]);
            acc[nf][3] = __expf(acc[nf][3] - mnew[1]);
            tsum[0] += acc[nf][0] + acc[nf][1];
            tsum[1] += acc[nf][2] + acc[nf][3];
        }
#pragma unroll
        for (int h = 0; h < 2; h++) {
            float v = tsum[h];
            v += __shfl_xor_sync(0xffffffffu, v, 1);
            v += __shfl_xor_sync(0xffffffffu, v, 2);
            s_run[h] += v;
            m_run[h] = mnew[h];
        }

        // --- store approx p tile (fp16) and rescale factors ---
        {
            const int row0 = m0 + wrow + lg;
            __half* P0 = P + (size_t)row0 * N_ADDR + t * 128 + lt * 2;
            __half* P1 = P0 + 8 * N_ADDR;
#pragma unroll
            for (int nf = 0; nf < 16; nf++) {
                *(__half2*)(P0 + nf * 8) = __floats2half2_rn(acc[nf][0], acc[nf][1]);
                *(__half2*)(P1 + nf * 8) = __floats2half2_rn(acc[nf][2], acc[nf][3]);
            }
        }
        if (lt == 0) {
            R[(size_t)t * M_TOT + m0 + wrow + lg]     = rfac[0];
            R[(size_t)t * M_TOT + m0 + wrow + lg + 8] = rfac[1];
        }
    }

    if (lt == 0) {
        SINV[m0 + wrow + lg]     = 1.0f / s_run[0];
        SINV[m0 + wrow + lg + 8] = 1.0f / s_run[1];
    }
}

// ---------------------------------------------------------------------------
// Pass 2: one warp per row (8 warps/CTA).
//   (1) suffix-scan R -> per-tile scale; scan P, compact cols w_approx > FTHR.
//   (2) exact fp32 rescore (warp-cooperative dots vs AS rows, L2-resident).
//   (3) exact softmax over list; (4) fp16 PB gather.
// ---------------------------------------------------------------------------
__global__ __launch_bounds__(256) void sparse_out(
    const __half* __restrict__ P, const float* __restrict__ R,
    const float* __restrict__ SINV,
    const float* __restrict__ SEL, const float* __restrict__ AS,
    const __half* __restrict__ PBH, float* __restrict__ C)
{
    __shared__ uint32_t s_col[8][LCAP];
    __shared__ float    s_s  [8][LCAP];
    __shared__ float    s_w  [8][LCAP];
    const int wline = threadIdx.x >> 5;
    const int lane  = threadIdx.x & 31;
    const int row   = blockIdx.x * 8 + wline;

    // --- per-tile scale via warp suffix-product scan (lane l <-> tile l) ---
    float prod = R[(size_t)lane * M_TOT + row];
#pragma unroll
    for (int o = 1; o < 32; o <<= 1) {
        float v = __shfl_down_sync(0xffffffffu, prod, o);
        if (lane + o < 32) prod *= v;
    }
    float suff = __shfl_down_sync(0xffffffffu, prod, 1);
    if (lane == 31) suff = 1.0f;
    const float scale_me = suff * SINV[row];

    // --- scan P row, ballot-compact survivors (w_approx > FTHR) ---
    int cnt = 0;
    const uint4* prow = (const uint4*)(P + (size_t)row * N_ADDR);
#pragma unroll
    for (int it = 0; it < 16; it++) {
        uint4 v = prow[it * 32 + lane];
        const int t = it * 2 + (lane >> 4);
        const float sc = __shfl_sync(0xffffffffu, scale_me, t);
        const uint32_t pk[4] = {v.x, v.y, v.z, v.w};
        const int cbase = it * 256 + lane * 8;
#pragma unroll
        for (int j = 0; j < 4; j++) {
            float2 f = __half22float2(*(const __half2*)&pk[j]);
            float w0 = f.x * sc, w1 = f.y * sc;
            unsigned b0 = __ballot_sync(0xffffffffu, w0 > FTHR);
            if (w0 > FTHR) {
                int pos = cnt + __popc(b0 & ((1u << lane) - 1u));
                if (pos < LCAP) s_col[wline][pos] = cbase + j * 2;
            }
            cnt += __popc(b0);
            unsigned b1 = __ballot_sync(0xffffffffu, w1 > FTHR);
            if (w1 > FTHR) {
                int pos = cnt + __popc(b1 & ((1u << lane) - 1u));
                if (pos < LCAP) s_col[wline][pos] = cbase + j * 2 + 1;
            }
            cnt += __popc(b1);
        }
    }
    if (cnt > LCAP) cnt = LCAP;
    __syncwarp();

    // --- exact fp32 rescore (warp-cooperative dot per survivor) ---
    const float4 sel = *(const float4*)(SEL + (size_t)row * D_DIM + lane * 4);
    float mx = -1e30f;
#pragma unroll 2
    for (int i = 0; i < cnt; i++) {
        const int col = (int)s_col[wline][i];
        float4 a = *(const float4*)(AS + (size_t)col * D_DIM + lane * 4);
        float s = a.x * sel.x + a.y * sel.y + a.z * sel.z + a.w * sel.w;
#pragma unroll
        for (int o = 16; o; o >>= 1) s += __shfl_xor_sync(0xffffffffu, s, o);
        if (lane == 0) s_s[wline][i] = s;
        mx = fmaxf(mx, s);
    }
    __syncwarp();

    // --- exact softmax over the list ---
    float part = 0.0f;
    for (int i = lane; i < cnt; i += 32) {
        float e = __expf(s_s[wline][i] - mx);
        s_w[wline][i] = e;
        part += e;
    }
#pragma unroll
    for (int o = 16; o; o >>= 1) part += __shfl_xor_sync(0xffffffffu, part, o);
    const float inv = 1.0f / part;
    __syncwarp();

    // --- fp16 PB gather (unroll x2 for MLP) ---
    float acc[16];
#pragma unroll
    for (int j = 0; j < 16; j++) acc[j] = 0.0f;

    int i = 0;
    for (; i + 2 <= cnt; i += 2) {
        const float w0 = s_w[wline][i] * inv, w1 = s_w[wline][i + 1] * inv;
        const __half* pb0 = PBH + (size_t)s_col[wline][i] * V_DIM + lane * 4;
        const __half* pb1 = PBH + (size_t)s_col[wline][i + 1] * V_DIM + lane * 4;
#pragma unroll
        for (int j = 0; j < 4; j++) {
            uint2 u0 = *(const uint2*)(pb0 + j * 128);
            uint2 u1 = *(const uint2*)(pb1 + j * 128);
            float2 a0 = __half22float2(*(const __half2*)&u0.x);
            float2 b0 = __half22float2(*(const __half2*)&u0.y);
            float2 a1 = __half22float2(*(const __half2*)&u1.x);
            float2 b1 = __half22float2(*(const __half2*)&u1.y);
            acc[j * 4 + 0] += w0 * a0.x + w1 * a1.x;
            acc[j * 4 + 1] += w0 * a0.y + w1 * a1.y;
            acc[j * 4 + 2] += w0 * b0.x + w1 * b1.x;
            acc[j * 4 + 3] += w0 * b0.y + w1 * b1.y;
        }
    }
    if (i < cnt) {
        const float w0 = s_w[wline][i] * inv;
        const __half* pb0 = PBH + (size_t)s_col[wline][i] * V_DIM + lane * 4;
#pragma unroll
        for (int j = 0; j < 4; j++) {
            uint2 u0 = *(const uint2*)(pb0 + j * 128);
            float2 a0 = __half22float2(*(const __half2*)&u0.x);
            float2 b0 = __half22float2(*(const __half2*)&u0.y);
            acc[j * 4 + 0] += w0 * a0.x;
            acc[j * 4 + 1] += w0 * a0.y;
            acc[j * 4 + 2] += w0 * b0.x;
            acc[j * 4 + 3] += w0 * b0.y;
        }
    }

    float* c = C + (size_t)row * V_DIM + lane * 4;
#pragma unroll
    for (int j = 0; j < 4; j++)
        *(float4*)(c + j * 128) = make_float4(acc[j * 4], acc[j * 4 + 1],
                                              acc[j * 4 + 2], acc[j * 4 + 3]);
}

// ---------------------------------------------------------------------------
// Prep: blocks [0,256) AS f32 -> fp16; blocks [256,1280) PB f32 -> fp16.
// ---------------------------------------------------------------------------
__global__ __launch_bounds__(256) void prep_kernel(
    const float* __restrict__ AS, __half* __restrict__ Hh,
    const float* __restrict__ PB, __half* __restrict__ PBH)
{
    if (blockIdx.x < 256) {
        const int i = blockIdx.x * 256 + threadIdx.x;   // 8 floats each
        const float4 v0 = ((const float4*)AS)[i * 2];
        const float4 v1 = ((const float4*)AS)[i * 2 + 1];
        __half2 h0 = __floats2half2_rn(v0.x, v0.y);
        __half2 h1 = __floats2half2_rn(v0.z, v0.w);
        __half2 h2 = __floats2half2_rn(v1.x, v1.y);
        __half2 h3 = __floats2half2_rn(v1.z, v1.w);
        ((uint4*)Hh)[i] = make_uint4(*(uint32_t*)&h0, *(uint32_t*)&h1,
                                     *(uint32_t*)&h2, *(uint32_t*)&h3);
    } else {
        const int i = (blockIdx.x - 256) * 256 + threadIdx.x;
        const float4 v0 = ((const float4*)PB)[i * 2];
        const float4 v1 = ((const float4*)PB)[i * 2 + 1];
        __half2 h0 = __floats2half2_rn(v0.x, v0.y);
        __half2 h1 = __floats2half2_rn(v0.z, v0.w);
        __half2 h2 = __floats2half2_rn(v1.x, v1.y);
        __half2 h3 = __floats2half2_rn(v1.z, v1.w);
        ((uint4*)PBH)[i] = make_uint4(*(uint32_t*)&h0, *(uint32_t*)&h1,
                                      *(uint32_t*)&h2, *(uint32_t*)&h3);
    }
}

// ---------------------------------------------------------------------------
extern "C" void kernel_launch(void* const* d_in, const int* in_sizes, int n_in,
                              void* d_out, int out_size)
{
    const float* selector      = (const float*)d_in[0];  // [16384, 128]
    const float* param_bank    = (const float*)d_in[1];  // [4096, 512]
    const float* address_space = (const float*)d_in[2];  // [4096, 128]
    float* out = (float*)d_out;                          // [16384, 512]

    __half* p;    cudaGetSymbolAddress((void**)&p,    g_p);
    __half* ash;  cudaGetSymbolAddress((void**)&ash,  g_ash);
    __half* pbh;  cudaGetSymbolAddress((void**)&pbh,  g_pbh);
    float*  rbuf; cudaGetSymbolAddress((void**)&rbuf, g_r);
    float*  sinv; cudaGetSymbolAddress((void**)&sinv, g_sinv);

    constexpr uint32_t SMEM1 = 98304;   // Sh (32K) + 2 B-stages (64K)
    cudaFuncSetAttribute(score_pass, cudaFuncAttributeMaxDynamicSharedMemorySize, SMEM1);

    prep_kernel<<<1280, 256>>>(address_space, ash, param_bank, pbh);

    score_pass<<<M_TOT / 128, 256, SMEM1>>>(selector, ash, p, rbuf, sinv);

    sparse_out<<<M_TOT / 8, 256>>>(p, rbuf, sinv, selector, address_space,
                                   pbh, out);
}

// round 16
// speedup vs baseline: 1.1083x; 1.1083x over previous
#include <cuda_runtime.h>
#include <cuda_fp16.h>
#include <cstdint>

// SoftAddressSpace: out[M,V] = softmax(selector[M,D] @ AS[N,D]^T) @ PB[N,V]
// M=16384, D=128, N=4096, V=512, fp32 in/out.
// R15: R13 (proven: 254us, 2.12e-4) with ONE knob: survivor threshold
//      1e-5 -> 3e-5. Measured sensitivity (R12->R13, 1e-6->1e-5): +1.1e-6
//      rel_err. Count model: ~41 survivors (LCAP 272 = 6.6x headroom).
//   pass1: 3-term fp16-split HMMA scores + online softmax -> fp16 p, R, SINV.
//   pass2: suffix-scan R -> per-tile scale; ballot-compact w > 3e-5;
//          gather w * PBH[col,:] (fp16).

#define M_TOT  16384
#define N_ADDR 4096
#define D_DIM  128
#define V_DIM  512
#define NTILES (N_ADDR / 128)   // 32
#define LCAP   272              // per-row survivor capacity
#define WTHR   3e-5f            // survivor weight threshold

static __device__ __half g_p   [(size_t)M_TOT * N_ADDR];   // fp16 p (128 MiB)
static __device__ __half g_ash [(size_t)N_ADDR * D_DIM];   // AS hi (1 MiB)
static __device__ __half g_asl [(size_t)N_ADDR * D_DIM];   // AS lo (1 MiB)
static __device__ __half g_pbh [(size_t)N_ADDR * V_DIM];   // PB fp16 (4 MiB)
static __device__ float  g_r   [(size_t)NTILES * M_TOT];   // rescale, [t][row]
static __device__ float  g_sinv[(size_t)M_TOT];            // 1/sum per row

__device__ __forceinline__ uint32_t smem_u32(const void* p) {
    uint32_t a;
    asm("{ .reg .u64 t; cvta.to.shared.u64 t, %1; cvt.u32.u64 %0, t; }" : "=r"(a) : "l"(p));
    return a;
}

#define LDSM_X4(r0, r1, r2, r3, addr) \
    asm volatile("ldmatrix.sync.aligned.m8n8.x4.shared.b16 {%0,%1,%2,%3}, [%4];" \
                 : "=r"(r0), "=r"(r1), "=r"(r2), "=r"(r3) : "r"(addr))

__device__ __forceinline__ void mma16816(float* d, const uint32_t* a, const uint32_t* b) {
    asm volatile(
        "mma.sync.aligned.m16n8k16.row.col.f32.f16.f16.f32 "
        "{%0,%1,%2,%3}, {%4,%5,%6,%7}, {%8,%9}, {%0,%1,%2,%3};"
        : "+f"(d[0]), "+f"(d[1]), "+f"(d[2]), "+f"(d[3])
        : "r"(a[0]), "r"(a[1]), "r"(a[2]), "r"(a[3]), "r"(b[0]), "r"(b[1]));
}

__device__ __forceinline__ void cp16(uint32_t dst, const void* src) {
    asm volatile("cp.async.cg.shared.global [%0], [%1], 16;" :: "r"(dst), "l"(src));
}
#define CP_COMMIT() asm volatile("cp.async.commit_group;" ::: "memory")
#define CP_WAIT0()  asm volatile("cp.async.wait_group 0;" ::: "memory")

// ---------------------------------------------------------------------------
// Pass 1 (identical to R9/R12/R13): grid = 128 CTAs, warp w owns rows
// [w*16,w*16+16). Smem: Sh @0 (32K), Sl @32K, B stages @64K (2 x [Bh|Bl] 64K).
// 256B smem rows; swizzle off ^ (((off>>8)&7)<<4). One syncthreads per tile.
// ---------------------------------------------------------------------------
__global__ __launch_bounds__(256, 1) void score_pass(
    const float* __restrict__ S,
    const __half* __restrict__ ASh, const __half* __restrict__ ASl,
    __half* __restrict__ P, float* __restrict__ R, float* __restrict__ SINV)
{
    extern __shared__ char sm[];
    const uint32_t sb = smem_u32(sm);
    const int tid = threadIdx.x, lane = tid & 31, wid = tid >> 5;
    const int m0 = blockIdx.x * 128;
    const int sub = lane >> 3, rr = lane & 7;
    const int lg = lane >> 2, lt = lane & 3;
    const int wrow = wid * 16;

    // --- load + hi/lo convert selector strip (resident) ---
#pragma unroll
    for (int s = 0; s < 8; s++) {
        int idx = tid + s * 256;
        int r = idx >> 4, b = idx & 15;
        uint32_t off = (uint32_t)(r * 256 + b * 16);
        uint32_t sw = off ^ (((off >> 8) & 7) << 4);
        const float* src = S + (size_t)(m0 + r) * D_DIM + b * 8;
        float4 v0 = *(const float4*)src, v1 = *(const float4*)(src + 4);
        float f[8] = {v0.x, v0.y, v0.z, v0.w, v1.x, v1.y, v1.z, v1.w};
        uint32_t hh[4], ll[4];
#pragma unroll
        for (int j = 0; j < 4; j++) {
            __half h0 = __float2half_rn(f[2 * j]);
            __half h1 = __float2half_rn(f[2 * j + 1]);
            __half l0 = __float2half_rn(f[2 * j]     - __half2float(h0));
            __half l1 = __float2half_rn(f[2 * j + 1] - __half2float(h1));
            __half2 hp = __halves2half2(h0, h1);
            __half2 lp = __halves2half2(l0, l1);
            hh[j] = *(uint32_t*)&hp; ll[j] = *(uint32_t*)&lp;
        }
        *(uint4*)(sm + sw)          = make_uint4(hh[0], hh[1], hh[2], hh[3]);
        *(uint4*)(sm + 32768u + sw) = make_uint4(ll[0], ll[1], ll[2], ll[3]);
    }

    auto issueB = [&](int st, int t) {
        const uint32_t base = 65536u + (uint32_t)st * 65536u;
#pragma unroll
        for (int s = 0; s < 8; s++) {
            int idx = tid + s * 256;
            int r = idx >> 4, b = idx & 15;
            uint32_t off = (uint32_t)(r * 256 + b * 16);
            uint32_t sw = off ^ (((off >> 8) & 7) << 4);
            const size_t go = (size_t)(t * 128 + r) * D_DIM + b * 8;
            cp16(sb + base + sw,          ASh + go);
            cp16(sb + base + 32768u + sw, ASl + go);
        }
        CP_COMMIT();
    };

    issueB(0, 0);

    float m_run[2] = {-1e30f, -1e30f}, s_run[2] = {0.0f, 0.0f};

    for (int t = 0; t < NTILES; t++) {
        CP_WAIT0();
        __syncthreads();
        if (t + 1 < NTILES) issueB((t + 1) & 1, t + 1);

        const uint32_t bbase = sb + 65536u + (uint32_t)(t & 1) * 65536u;

        float acc[16][4];
#pragma unroll
        for (int i = 0; i < 16; i++)
#pragma unroll
            for (int k = 0; k < 4; k++) acc[i][k] = 0.0f;

#pragma unroll
        for (int ks = 0; ks < 8; ks++) {
            uint32_t ah[4], al[4], bh[32], bl[32];
            {
                int row = wrow + ((sub & 1) << 3) + rr;
                uint32_t off = (uint32_t)(row * 256 + ks * 32 + ((sub >> 1) << 4));
                uint32_t sw = off ^ (((off >> 8) & 7) << 4);
                LDSM_X4(ah[0], ah[1], ah[2], ah[3], sb + sw);
                LDSM_X4(al[0], al[1], al[2], al[3], sb + 32768u + sw);
            }
#pragma unroll
            for (int p2 = 0; p2 < 8; p2++) {
                int nrow = p2 * 16 + ((sub >> 1) << 3) + rr;
                uint32_t off = (uint32_t)(nrow * 256 + ks * 32 + ((sub & 1) << 4));
                uint32_t sw = off ^ (((off >> 8) & 7) << 4);
                LDSM_X4(bh[p2 * 4], bh[p2 * 4 + 1], bh[p2 * 4 + 2], bh[p2 * 4 + 3], bbase + sw);
                LDSM_X4(bl[p2 * 4], bl[p2 * 4 + 1], bl[p2 * 4 + 2], bl[p2 * 4 + 3], bbase + 32768u + sw);
            }
#pragma unroll
            for (int nf = 0; nf < 16; nf++) {
                mma16816(acc[nf], ah, &bh[nf * 2]);
                mma16816(acc[nf], ah, &bl[nf * 2]);
                mma16816(acc[nf], al, &bh[nf * 2]);
            }
        }

        // --- warp-local online softmax (rows: wrow+lg, wrow+lg+8) ---
        float mnew[2], rfac[2], tsum[2];
#pragma unroll
        for (int h = 0; h < 2; h++) {
            float v = -1e30f;
#pragma unroll
            for (int nf = 0; nf < 16; nf++)
                v = fmaxf(v, fmaxf(acc[nf][2 * h], acc[nf][2 * h + 1]));
            v = fmaxf(v, __shfl_xor_sync(0xffffffffu, v, 1));
            v = fmaxf(v, __shfl_xor_sync(0xffffffffu, v, 2));
            float mn = fmaxf(m_run[h], v);
            mnew[h] = mn;
            rfac[h] = __expf(m_run[h] - mn);
            s_run[h] *= rfac[h];
            tsum[h] = 0.0f;
        }
#pragma unroll
        for (int nf = 0; nf < 16; nf++) {
            acc[nf][0] = __expf(acc[nf][0] - mnew[0]);
            acc[nf][1] = __expf(acc[nf][1] - mnew[0]);
            acc[nf][2] = __expf(acc[nf][2] - mnew[1]);
            acc[nf][3] = __expf(acc[nf][3] - mnew[1]);
            tsum[0] += acc[nf][0] + acc[nf][1];
            tsum[1] += acc[nf][2] + acc[nf][3];
        }
#pragma unroll
        for (int h = 0; h < 2; h++) {
            float v = tsum[h];
            v += __shfl_xor_sync(0xffffffffu, v, 1);
            v += __shfl_xor_sync(0xffffffffu, v, 2);
            s_run[h] += v;
            m_run[h] = mnew[h];
        }

        // --- store p tile (fp16) and rescale factors ---
        {
            const int row0 = m0 + wrow + lg;
            __half* P0 = P + (size_t)row0 * N_ADDR + t * 128 + lt * 2;
            __half* P1 = P0 + 8 * N_ADDR;
#pragma unroll
            for (int nf = 0; nf < 16; nf++) {
                *(__half2*)(P0 + nf * 8) = __floats2half2_rn(acc[nf][0], acc[nf][1]);
                *(__half2*)(P1 + nf * 8) = __floats2half2_rn(acc[nf][2], acc[nf][3]);
            }
        }
        if (lt == 0) {
            R[(size_t)t * M_TOT + m0 + wrow + lg]     = rfac[0];
            R[(size_t)t * M_TOT + m0 + wrow + lg + 8] = rfac[1];
        }
    }

    if (lt == 0) {
        SINV[m0 + wrow + lg]     = 1.0f / s_run[0];
        SINV[m0 + wrow + lg + 8] = 1.0f / s_run[1];
    }
}

// ---------------------------------------------------------------------------
// Pass 2 (identical to R13 except WTHR): one warp per row (8 warps/CTA).
//   scale[t] = (suffix product of R over t' > t) * sinv   (warp shfl scan)
//   stream P row; survivors (w = p*scale > WTHR) ballot-compacted into smem;
//   gather-accumulate w * PBH[col, :] (fp16, L2-resident).
// ---------------------------------------------------------------------------
__global__ __launch_bounds__(256) void sparse_out(
    const __half* __restrict__ P, const float* __restrict__ R,
    const float* __restrict__ SINV, const __half* __restrict__ PBH,
    float* __restrict__ C)
{
    __shared__ uint32_t s_col[8][LCAP];
    __shared__ float    s_w  [8][LCAP];
    const int wline = threadIdx.x >> 5;
    const int lane  = threadIdx.x & 31;
    const int row   = blockIdx.x * 8 + wline;

    // --- per-tile scale via warp suffix-product scan (lane l <-> tile l) ---
    float prod = R[(size_t)lane * M_TOT + row];
#pragma unroll
    for (int o = 1; o < 32; o <<= 1) {
        float v = __shfl_down_sync(0xffffffffu, prod, o);
        if (lane + o < 32) prod *= v;
    }
    float suff = __shfl_down_sync(0xffffffffu, prod, 1);   // g_{l+1}
    if (lane == 31) suff = 1.0f;
    const float scale_me = suff * SINV[row];

    // --- scan P row, compact survivors ---
    int cnt = 0;
    const uint4* prow = (const uint4*)(P + (size_t)row * N_ADDR);
#pragma unroll
    for (int it = 0; it < 16; it++) {
        uint4 v = prow[it * 32 + lane];
        const int t = it * 2 + (lane >> 4);                 // tile of this lane's 8 vals
        const float sc = __shfl_sync(0xffffffffu, scale_me, t);
        const uint32_t pk[4] = {v.x, v.y, v.z, v.w};
        const int cbase = it * 256 + lane * 8;
#pragma unroll
        for (int j = 0; j < 4; j++) {
            float2 f = __half22float2(*(const __half2*)&pk[j]);
            float w0 = f.x * sc, w1 = f.y * sc;
            unsigned b0 = __ballot_sync(0xffffffffu, w0 > WTHR);
            if (w0 > WTHR) {
                int pos = cnt + __popc(b0 & ((1u << lane) - 1u));
                if (pos < LCAP) { s_col[wline][pos] = cbase + j * 2; s_w[wline][pos] = w0; }
            }
            cnt += __popc(b0);
            unsigned b1 = __ballot_sync(0xffffffffu, w1 > WTHR);
            if (w1 > WTHR) {
                int pos = cnt + __popc(b1 & ((1u << lane) - 1u));
                if (pos < LCAP) { s_col[wline][pos] = cbase + j * 2 + 1; s_w[wline][pos] = w1; }
            }
            cnt += __popc(b1);
        }
    }
    if (cnt > LCAP) cnt = LCAP;
    __syncwarp();

    // --- gather-accumulate from fp16 PB (unroll x2 for MLP) ---
    float acc[16];
#pragma unroll
    for (int j = 0; j < 16; j++) acc[j] = 0.0f;

    int i = 0;
    for (; i + 2 <= cnt; i += 2) {
        const uint32_t c0 = s_col[wline][i],     c1 = s_col[wline][i + 1];
        const float    w0 = s_w  [wline][i],     w1 = s_w  [wline][i + 1];
        const __half* pb0 = PBH + (size_t)c0 * V_DIM + lane * 4;
        const __half* pb1 = PBH + (size_t)c1 * V_DIM + lane * 4;
#pragma unroll
        for (int j = 0; j < 4; j++) {
            uint2 u0 = *(const uint2*)(pb0 + j * 128);
            uint2 u1 = *(const uint2*)(pb1 + j * 128);
            float2 a0 = __half22float2(*(const __half2*)&u0.x);
            float2 b0 = __half22float2(*(const __half2*)&u0.y);
            float2 a1 = __half22float2(*(const __half2*)&u1.x);
            float2 b1 = __half22float2(*(const __half2*)&u1.y);
            acc[j * 4 + 0] += w0 * a0.x + w1 * a1.x;
            acc[j * 4 + 1] += w0 * a0.y + w1 * a1.y;
            acc[j * 4 + 2] += w0 * b0.x + w1 * b1.x;
            acc[j * 4 + 3] += w0 * b0.y + w1 * b1.y;
        }
    }
    if (i < cnt) {
        const uint32_t c0 = s_col[wline][i];
        const float    w0 = s_w  [wline][i];
        const __half* pb0 = PBH + (size_t)c0 * V_DIM + lane * 4;
#pragma unroll
        for (int j = 0; j < 4; j++) {
            uint2 u0 = *(const uint2*)(pb0 + j * 128);
            float2 a0 = __half22float2(*(const __half2*)&u0.x);
            float2 b0 = __half22float2(*(const __half2*)&u0.y);
            acc[j * 4 + 0] += w0 * a0.x;
            acc[j * 4 + 1] += w0 * a0.y;
            acc[j * 4 + 2] += w0 * b0.x;
            acc[j * 4 + 3] += w0 * b0.y;
        }
    }

    float* c = C + (size_t)row * V_DIM + lane * 4;
#pragma unroll
    for (int j = 0; j < 4; j++)
        *(float4*)(c + j * 128) = make_float4(acc[j * 4], acc[j * 4 + 1],
                                              acc[j * 4 + 2], acc[j * 4 + 3]);
}

// ---------------------------------------------------------------------------
// Prep: blocks [0,256) AS f32 -> hi/lo fp16; blocks [256,1280) PB f32 -> fp16.
// ---------------------------------------------------------------------------
__global__ __launch_bounds__(256) void prep_kernel(
    const float* __restrict__ AS, __half* __restrict__ Hh, __half* __restrict__ Hl,
    const float* __restrict__ PB, __half* __restrict__ PBH)
{
    if (blockIdx.x < 256) {
        const int i = blockIdx.x * 256 + threadIdx.x;   // 8 floats each
        const float4 v0 = ((const float4*)AS)[i * 2];
        const float4 v1 = ((const float4*)AS)[i * 2 + 1];
        float f[8] = {v0.x, v0.y, v0.z, v0.w, v1.x, v1.y, v1.z, v1.w};
        uint32_t hh[4], ll[4];
#pragma unroll
        for (int j = 0; j < 4; j++) {
            __half h0 = __float2half_rn(f[2 * j]);
            __half h1 = __float2half_rn(f[2 * j + 1]);
            __half l0 = __float2half_rn(f[2 * j]     - __half2float(h0));
            __half l1 = __float2half_rn(f[2 * j + 1] - __half2float(h1));
            __half2 hp = __halves2half2(h0, h1);
            __half2 lp = __halves2half2(l0, l1);
            hh[j] = *(uint32_t*)&hp; ll[j] = *(uint32_t*)&lp;
        }
        ((uint4*)Hh)[i] = make_uint4(hh[0], hh[1], hh[2], hh[3]);
        ((uint4*)Hl)[i] = make_uint4(ll[0], ll[1], ll[2], ll[3]);
    } else {
        const int i = (blockIdx.x - 256) * 256 + threadIdx.x;  // 8 floats each
        const float4 v0 = ((const float4*)PB)[i * 2];
        const float4 v1 = ((const float4*)PB)[i * 2 + 1];
        __half2 h0 = __floats2half2_rn(v0.x, v0.y);
        __half2 h1 = __floats2half2_rn(v0.z, v0.w);
        __half2 h2 = __floats2half2_rn(v1.x, v1.y);
        __half2 h3 = __floats2half2_rn(v1.z, v1.w);
        ((uint4*)PBH)[i] = make_uint4(*(uint32_t*)&h0, *(uint32_t*)&h1,
                                      *(uint32_t*)&h2, *(uint32_t*)&h3);
    }
}

// ---------------------------------------------------------------------------
extern "C" void kernel_launch(void* const* d_in, const int* in_sizes, int n_in,
                              void* d_out, int out_size)
{
    const float* selector      = (const float*)d_in[0];  // [16384, 128]
    const float* param_bank    = (const float*)d_in[1];  // [4096, 512]
    const float* address_space = (const float*)d_in[2];  // [4096, 128]
    float* out = (float*)d_out;                          // [16384, 512]

    __half* p;    cudaGetSymbolAddress((void**)&p,    g_p);
    __half* ash;  cudaGetSymbolAddress((void**)&ash,  g_ash);
    __half* asl;  cudaGetSymbolAddress((void**)&asl,  g_asl);
    __half* pbh;  cudaGetSymbolAddress((void**)&pbh,  g_pbh);
    float*  rbuf; cudaGetSymbolAddress((void**)&rbuf, g_r);
    float*  sinv; cudaGetSymbolAddress((void**)&sinv, g_sinv);

    constexpr uint32_t SMEM1 = 196608;  // Sh+Sl (64K) + 2 B-stages (128K)
    cudaFuncSetAttribute(score_pass, cudaFuncAttributeMaxDynamicSharedMemorySize, SMEM1);

    prep_kernel<<<1280, 256>>>(address_space, ash, asl, param_bank, pbh);

    score_pass<<<M_TOT / 128, 256, SMEM1>>>(selector, ash, asl, p, rbuf, sinv);

    sparse_out<<<M_TOT / 8, 256>>>(p, rbuf, sinv, pbh, out);
}

// round 17
// speedup vs baseline: 1.1614x; 1.0479x over previous
#include <cuda_runtime.h>
#include <cuda_fp16.h>
#include <cstdint>

// SoftAddressSpace: out[M,V] = softmax(selector[M,D] @ AS[N,D]^T) @ PB[N,V]
// M=16384, D=128, N=4096, V=512, fp32 in/out.
// R16: R15 (proven: 244us, 2.19e-4) with two knobs:
//   (1) survivor threshold 3e-5 -> 1e-4 (twice-measured sensitivity:
//       1e-6->1e-5 = +1.1e-6, 1e-5->3e-5 = +6.7e-6; expect +~2e-5).
//   (2) pass2 gather unroll x2 -> x4 (double outstanding LDG -> higher
//       effective L2 BW at same traffic).
//   pass1: 3-term fp16-split HMMA scores + online softmax -> fp16 p, R, SINV.
//   pass2: suffix-scan R -> per-tile scale; ballot-compact w > 1e-4;
//          gather w * PBH[col,:] (fp16), unroll x4.

#define M_TOT  16384
#define N_ADDR 4096
#define D_DIM  128
#define V_DIM  512
#define NTILES (N_ADDR / 128)   // 32
#define LCAP   272              // per-row survivor capacity
#define WTHR   1e-4f            // survivor weight threshold

static __device__ __half g_p   [(size_t)M_TOT * N_ADDR];   // fp16 p (128 MiB)
static __device__ __half g_ash [(size_t)N_ADDR * D_DIM];   // AS hi (1 MiB)
static __device__ __half g_asl [(size_t)N_ADDR * D_DIM];   // AS lo (1 MiB)
static __device__ __half g_pbh [(size_t)N_ADDR * V_DIM];   // PB fp16 (4 MiB)
static __device__ float  g_r   [(size_t)NTILES * M_TOT];   // rescale, [t][row]
static __device__ float  g_sinv[(size_t)M_TOT];            // 1/sum per row

__device__ __forceinline__ uint32_t smem_u32(const void* p) {
    uint32_t a;
    asm("{ .reg .u64 t; cvta.to.shared.u64 t, %1; cvt.u32.u64 %0, t; }" : "=r"(a) : "l"(p));
    return a;
}

#define LDSM_X4(r0, r1, r2, r3, addr) \
    asm volatile("ldmatrix.sync.aligned.m8n8.x4.shared.b16 {%0,%1,%2,%3}, [%4];" \
                 : "=r"(r0), "=r"(r1), "=r"(r2), "=r"(r3) : "r"(addr))

__device__ __forceinline__ void mma16816(float* d, const uint32_t* a, const uint32_t* b) {
    asm volatile(
        "mma.sync.aligned.m16n8k16.row.col.f32.f16.f16.f32 "
        "{%0,%1,%2,%3}, {%4,%5,%6,%7}, {%8,%9}, {%0,%1,%2,%3};"
        : "+f"(d[0]), "+f"(d[1]), "+f"(d[2]), "+f"(d[3])
        : "r"(a[0]), "r"(a[1]), "r"(a[2]), "r"(a[3]), "r"(b[0]), "r"(b[1]));
}

__device__ __forceinline__ void cp16(uint32_t dst, const void* src) {
    asm volatile("cp.async.cg.shared.global [%0], [%1], 16;" :: "r"(dst), "l"(src));
}
#define CP_COMMIT() asm volatile("cp.async.commit_group;" ::: "memory")
#define CP_WAIT0()  asm volatile("cp.async.wait_group 0;" ::: "memory")

// ---------------------------------------------------------------------------
// Pass 1 (identical to R13/R15): grid = 128 CTAs, warp w owns rows
// [w*16,w*16+16). Smem: Sh @0 (32K), Sl @32K, B stages @64K (2 x [Bh|Bl] 64K).
// 256B smem rows; swizzle off ^ (((off>>8)&7)<<4). One syncthreads per tile.
// ---------------------------------------------------------------------------
__global__ __launch_bounds__(256, 1) void score_pass(
    const float* __restrict__ S,
    const __half* __restrict__ ASh, const __half* __restrict__ ASl,
    __half* __restrict__ P, float* __restrict__ R, float* __restrict__ SINV)
{
    extern __shared__ char sm[];
    const uint32_t sb = smem_u32(sm);
    const int tid = threadIdx.x, lane = tid & 31, wid = tid >> 5;
    const int m0 = blockIdx.x * 128;
    const int sub = lane >> 3, rr = lane & 7;
    const int lg = lane >> 2, lt = lane & 3;
    const int wrow = wid * 16;

    // --- load + hi/lo convert selector strip (resident) ---
#pragma unroll
    for (int s = 0; s < 8; s++) {
        int idx = tid + s * 256;
        int r = idx >> 4, b = idx & 15;
        uint32_t off = (uint32_t)(r * 256 + b * 16);
        uint32_t sw = off ^ (((off >> 8) & 7) << 4);
        const float* src = S + (size_t)(m0 + r) * D_DIM + b * 8;
        float4 v0 = *(const float4*)src, v1 = *(const float4*)(src + 4);
        float f[8] = {v0.x, v0.y, v0.z, v0.w, v1.x, v1.y, v1.z, v1.w};
        uint32_t hh[4], ll[4];
#pragma unroll
        for (int j = 0; j < 4; j++) {
            __half h0 = __float2half_rn(f[2 * j]);
            __half h1 = __float2half_rn(f[2 * j + 1]);
            __half l0 = __float2half_rn(f[2 * j]     - __half2float(h0));
            __half l1 = __float2half_rn(f[2 * j + 1] - __half2float(h1));
            __half2 hp = __halves2half2(h0, h1);
            __half2 lp = __halves2half2(l0, l1);
            hh[j] = *(uint32_t*)&hp; ll[j] = *(uint32_t*)&lp;
        }
        *(uint4*)(sm + sw)          = make_uint4(hh[0], hh[1], hh[2], hh[3]);
        *(uint4*)(sm + 32768u + sw) = make_uint4(ll[0], ll[1], ll[2], ll[3]);
    }

    auto issueB = [&](int st, int t) {
        const uint32_t base = 65536u + (uint32_t)st * 65536u;
#pragma unroll
        for (int s = 0; s < 8; s++) {
            int idx = tid + s * 256;
            int r = idx >> 4, b = idx & 15;
            uint32_t off = (uint32_t)(r * 256 + b * 16);
            uint32_t sw = off ^ (((off >> 8) & 7) << 4);
            const size_t go = (size_t)(t * 128 + r) * D_DIM + b * 8;
            cp16(sb + base + sw,          ASh + go);
            cp16(sb + base + 32768u + sw, ASl + go);
        }
        CP_COMMIT();
    };

    issueB(0, 0);

    float m_run[2] = {-1e30f, -1e30f}, s_run[2] = {0.0f, 0.0f};

    for (int t = 0; t < NTILES; t++) {
        CP_WAIT0();
        __syncthreads();
        if (t + 1 < NTILES) issueB((t + 1) & 1, t + 1);

        const uint32_t bbase = sb + 65536u + (uint32_t)(t & 1) * 65536u;

        float acc[16][4];
#pragma unroll
        for (int i = 0; i < 16; i++)
#pragma unroll
            for (int k = 0; k < 4; k++) acc[i][k] = 0.0f;

#pragma unroll
        for (int ks = 0; ks < 8; ks++) {
            uint32_t ah[4], al[4], bh[32], bl[32];
            {
                int row = wrow + ((sub & 1) << 3) + rr;
                uint32_t off = (uint32_t)(row * 256 + ks * 32 + ((sub >> 1) << 4));
                uint32_t sw = off ^ (((off >> 8) & 7) << 4);
                LDSM_X4(ah[0], ah[1], ah[2], ah[3], sb + sw);
                LDSM_X4(al[0], al[1], al[2], al[3], sb + 32768u + sw);
            }
#pragma unroll
            for (int p2 = 0; p2 < 8; p2++) {
                int nrow = p2 * 16 + ((sub >> 1) << 3) + rr;
                uint32_t off = (uint32_t)(nrow * 256 + ks * 32 + ((sub & 1) << 4));
                uint32_t sw = off ^ (((off >> 8) & 7) << 4);
                LDSM_X4(bh[p2 * 4], bh[p2 * 4 + 1], bh[p2 * 4 + 2], bh[p2 * 4 + 3], bbase + sw);
                LDSM_X4(bl[p2 * 4], bl[p2 * 4 + 1], bl[p2 * 4 + 2], bl[p2 * 4 + 3], bbase + 32768u + sw);
            }
#pragma unroll
            for (int nf = 0; nf < 16; nf++) {
                mma16816(acc[nf], ah, &bh[nf * 2]);
                mma16816(acc[nf], ah, &bl[nf * 2]);
                mma16816(acc[nf], al, &bh[nf * 2]);
            }
        }

        // --- warp-local online softmax (rows: wrow+lg, wrow+lg+8) ---
        float mnew[2], rfac[2], tsum[2];
#pragma unroll
        for (int h = 0; h < 2; h++) {
            float v = -1e30f;
#pragma unroll
            for (int nf = 0; nf < 16; nf++)
                v = fmaxf(v, fmaxf(acc[nf][2 * h], acc[nf][2 * h + 1]));
            v = fmaxf(v, __shfl_xor_sync(0xffffffffu, v, 1));
            v = fmaxf(v, __shfl_xor_sync(0xffffffffu, v, 2));
            float mn = fmaxf(m_run[h], v);
            mnew[h] = mn;
            rfac[h] = __expf(m_run[h] - mn);
            s_run[h] *= rfac[h];
            tsum[h] = 0.0f;
        }
#pragma unroll
        for (int nf = 0; nf < 16; nf++) {
            acc[nf][0] = __expf(acc[nf][0] - mnew[0]);
            acc[nf][1] = __expf(acc[nf][1] - mnew[0]);
            acc[nf][2] = __expf(acc[nf][2] - mnew[1]);
            acc[nf][3] = __expf(acc[nf][3] - mnew[1]);
            tsum[0] += acc[nf][0] + acc[nf][1];
            tsum[1] += acc[nf][2] + acc[nf][3];
        }
#pragma unroll
        for (int h = 0; h < 2; h++) {
            float v = tsum[h];
            v += __shfl_xor_sync(0xffffffffu, v, 1);
            v += __shfl_xor_sync(0xffffffffu, v, 2);
            s_run[h] += v;
            m_run[h] = mnew[h];
        }

        // --- store p tile (fp16) and rescale factors ---
        {
            const int row0 = m0 + wrow + lg;
            __half* P0 = P + (size_t)row0 * N_ADDR + t * 128 + lt * 2;
            __half* P1 = P0 + 8 * N_ADDR;
#pragma unroll
            for (int nf = 0; nf < 16; nf++) {
                *(__half2*)(P0 + nf * 8) = __floats2half2_rn(acc[nf][0], acc[nf][1]);
                *(__half2*)(P1 + nf * 8) = __floats2half2_rn(acc[nf][2], acc[nf][3]);
            }
        }
        if (lt == 0) {
            R[(size_t)t * M_TOT + m0 + wrow + lg]     = rfac[0];
            R[(size_t)t * M_TOT + m0 + wrow + lg + 8] = rfac[1];
        }
    }

    if (lt == 0) {
        SINV[m0 + wrow + lg]     = 1.0f / s_run[0];
        SINV[m0 + wrow + lg + 8] = 1.0f / s_run[1];
    }
}

// ---------------------------------------------------------------------------
// Pass 2: one warp per row (8 warps/CTA).
//   scale[t] = (suffix product of R over t' > t) * sinv   (warp shfl scan)
//   stream P row; survivors (w = p*scale > WTHR) ballot-compacted into smem;
//   gather-accumulate w * PBH[col, :] (fp16, L2-resident), unroll x4.
// ---------------------------------------------------------------------------
__global__ __launch_bounds__(256) void sparse_out(
    const __half* __restrict__ P, const float* __restrict__ R,
    const float* __restrict__ SINV, const __half* __restrict__ PBH,
    float* __restrict__ C)
{
    __shared__ uint32_t s_col[8][LCAP];
    __shared__ float    s_w  [8][LCAP];
    const int wline = threadIdx.x >> 5;
    const int lane  = threadIdx.x & 31;
    const int row   = blockIdx.x * 8 + wline;

    // --- per-tile scale via warp suffix-product scan (lane l <-> tile l) ---
    float prod = R[(size_t)lane * M_TOT + row];
#pragma unroll
    for (int o = 1; o < 32; o <<= 1) {
        float v = __shfl_down_sync(0xffffffffu, prod, o);
        if (lane + o < 32) prod *= v;
    }
    float suff = __shfl_down_sync(0xffffffffu, prod, 1);   // g_{l+1}
    if (lane == 31) suff = 1.0f;
    const float scale_me = suff * SINV[row];

    // --- scan P row, compact survivors ---
    int cnt = 0;
    const uint4* prow = (const uint4*)(P + (size_t)row * N_ADDR);
#pragma unroll
    for (int it = 0; it < 16; it++) {
        uint4 v = prow[it * 32 + lane];
        const int t = it * 2 + (lane >> 4);                 // tile of this lane's 8 vals
        const float sc = __shfl_sync(0xffffffffu, scale_me, t);
        const uint32_t pk[4] = {v.x, v.y, v.z, v.w};
        const int cbase = it * 256 + lane * 8;
#pragma unroll
        for (int j = 0; j < 4; j++) {
            float2 f = __half22float2(*(const __half2*)&pk[j]);
            float w0 = f.x * sc, w1 = f.y * sc;
            unsigned b0 = __ballot_sync(0xffffffffu, w0 > WTHR);
            if (w0 > WTHR) {
                int pos = cnt + __popc(b0 & ((1u << lane) - 1u));
                if (pos < LCAP) { s_col[wline][pos] = cbase + j * 2; s_w[wline][pos] = w0; }
            }
            cnt += __popc(b0);
            unsigned b1 = __ballot_sync(0xffffffffu, w1 > WTHR);
            if (w1 > WTHR) {
                int pos = cnt + __popc(b1 & ((1u << lane) - 1u));
                if (pos < LCAP) { s_col[wline][pos] = cbase + j * 2 + 1; s_w[wline][pos] = w1; }
            }
            cnt += __popc(b1);
        }
    }
    if (cnt > LCAP) cnt = LCAP;
    __syncwarp();

    // --- gather-accumulate from fp16 PB (unroll x4 for MLP) ---
    float acc[16];
#pragma unroll
    for (int j = 0; j < 16; j++) acc[j] = 0.0f;

    int i = 0;
    for (; i + 4 <= cnt; i += 4) {
        float    w[4];
        const __half* pb[4];
#pragma unroll
        for (int q = 0; q < 4; q++) {
            w[q]  = s_w[wline][i + q];
            pb[q] = PBH + (size_t)s_col[wline][i + q] * V_DIM + lane * 4;
        }
#pragma unroll
        for (int j = 0; j < 4; j++) {
            uint2 u[4];
#pragma unroll
            for (int q = 0; q < 4; q++) u[q] = *(const uint2*)(pb[q] + j * 128);
#pragma unroll
            for (int q = 0; q < 4; q++) {
                float2 a = __half22float2(*(const __half2*)&u[q].x);
                float2 b = __half22float2(*(const __half2*)&u[q].y);
                acc[j * 4 + 0] += w[q] * a.x;
                acc[j * 4 + 1] += w[q] * a.y;
                acc[j * 4 + 2] += w[q] * b.x;
                acc[j * 4 + 3] += w[q] * b.y;
            }
        }
    }
    for (; i < cnt; i++) {
        const float    w0 = s_w[wline][i];
        const __half* pb0 = PBH + (size_t)s_col[wline][i] * V_DIM + lane * 4;
#pragma unroll
        for (int j = 0; j < 4; j++) {
            uint2 u0 = *(const uint2*)(pb0 + j * 128);
            float2 a0 = __half22float2(*(const __half2*)&u0.x);
            float2 b0 = __half22float2(*(const __half2*)&u0.y);
            acc[j * 4 + 0] += w0 * a0.x;
            acc[j * 4 + 1] += w0 * a0.y;
            acc[j * 4 + 2] += w0 * b0.x;
            acc[j * 4 + 3] += w0 * b0.y;
        }
    }

    float* c = C + (size_t)row * V_DIM + lane * 4;
#pragma unroll
    for (int j = 0; j < 4; j++)
        *(float4*)(c + j * 128) = make_float4(acc[j * 4], acc[j * 4 + 1],
                                              acc[j * 4 + 2], acc[j * 4 + 3]);
}

// ---------------------------------------------------------------------------
// Prep: blocks [0,256) AS f32 -> hi/lo fp16; blocks [256,1280) PB f32 -> fp16.
// ---------------------------------------------------------------------------
__global__ __launch_bounds__(256) void prep_kernel(
    const float* __restrict__ AS, __half* __restrict__ Hh, __half* __restrict__ Hl,
    const float* __restrict__ PB, __half* __restrict__ PBH)
{
    if (blockIdx.x < 256) {
        const int i = blockIdx.x * 256 + threadIdx.x;   // 8 floats each
        const float4 v0 = ((const float4*)AS)[i * 2];
        const float4 v1 = ((const float4*)AS)[i * 2 + 1];
        float f[8] = {v0.x, v0.y, v0.z, v0.w, v1.x, v1.y, v1.z, v1.w};
        uint32_t hh[4], ll[4];
#pragma unroll
        for (int j = 0; j < 4; j++) {
            __half h0 = __float2half_rn(f[2 * j]);
            __half h1 = __float2half_rn(f[2 * j + 1]);
            __half l0 = __float2half_rn(f[2 * j]     - __half2float(h0));
            __half l1 = __float2half_rn(f[2 * j + 1] - __half2float(h1));
            __half2 hp = __halves2half2(h0, h1);
            __half2 lp = __halves2half2(l0, l1);
            hh[j] = *(uint32_t*)&hp; ll[j] = *(uint32_t*)&lp;
        }
        ((uint4*)Hh)[i] = make_uint4(hh[0], hh[1], hh[2], hh[3]);
        ((uint4*)Hl)[i] = make_uint4(ll[0], ll[1], ll[2], ll[3]);
    } else {
        const int i = (blockIdx.x - 256) * 256 + threadIdx.x;  // 8 floats each
        const float4 v0 = ((const float4*)PB)[i * 2];
        const float4 v1 = ((const float4*)PB)[i * 2 + 1];
        __half2 h0 = __floats2half2_rn(v0.x, v0.y);
        __half2 h1 = __floats2half2_rn(v0.z, v0.w);
        __half2 h2 = __floats2half2_rn(v1.x, v1.y);
        __half2 h3 = __floats2half2_rn(v1.z, v1.w);
        ((uint4*)PBH)[i] = make_uint4(*(uint32_t*)&h0, *(uint32_t*)&h1,
                                      *(uint32_t*)&h2, *(uint32_t*)&h3);
    }
}

// ---------------------------------------------------------------------------
extern "C" void kernel_launch(void* const* d_in, const int* in_sizes, int n_in,
                              void* d_out, int out_size)
{
    const float* selector      = (const float*)d_in[0];  // [16384, 128]
    const float* param_bank    = (const float*)d_in[1];  // [4096, 512]
    const float* address_space = (const float*)d_in[2];  // [4096, 128]
    float* out = (float*)d_out;                          // [16384, 512]

    __half* p;    cudaGetSymbolAddress((void**)&p,    g_p);
    __half* ash;  cudaGetSymbolAddress((void**)&ash,  g_ash);
    __half* asl;  cudaGetSymbolAddress((void**)&asl,  g_asl);
    __half* pbh;  cudaGetSymbolAddress((void**)&pbh,  g_pbh);
    float*  rbuf; cudaGetSymbolAddress((void**)&rbuf, g_r);
    float*  sinv; cudaGetSymbolAddress((void**)&sinv, g_sinv);

    constexpr uint32_t SMEM1 = 196608;  // Sh+Sl (64K) + 2 B-stages (128K)
    cudaFuncSetAttribute(score_pass, cudaFuncAttributeMaxDynamicSharedMemorySize, SMEM1);

    prep_kernel<<<1280, 256>>>(address_space, ash, asl, param_bank, pbh);

    score_pass<<<M_TOT / 128, 256, SMEM1>>>(selector, ash, asl, p, rbuf, sinv);

    sparse_out<<<M_TOT / 8, 256>>>(p, rbuf, sinv, pbh, out);
}